// round 14
// baseline (speedup 1.0000x reference)
#include <cuda_runtime.h>
#include <cuda_fp16.h>

#define NN  50000
#define EE  800000
#define DIN 32
#define F   128      // HEADS * DIM_H
#define NPB 50       // nodes per block in transform1
#define CAP 64       // padded bucket capacity (deg incl. self; P(>=64) ~ 1e-17)

// ---------------- scratch (device globals; no allocation allowed) ----------
__device__ __align__(16) __half g_xl1h[NN * F];   // fp16 gather table
__device__ __align__(16) __half g_xr1h[NN * F];   // fp16 dest table
__device__ float g_xl2[NN];
__device__ float g_xr2[NN];
__device__ __align__(16) int g_deg[NN];           // zeroed by k_agg2 epilogue
__device__ __align__(16) int g_bkt[NN * CAP];     // padded per-dst edge lists

__device__ __forceinline__ float lrelu(float x) { return fmaxf(x, 0.2f * x); }

// ---- f32x2 packed helpers (Blackwell; PTX-only) ----------------------------
__device__ __forceinline__ unsigned long long pk2(float lo, float hi) {
    unsigned long long r;
    asm("mov.b64 %0, {%1, %2};" : "=l"(r) : "f"(lo), "f"(hi));
    return r;
}
__device__ __forceinline__ void upk2(unsigned long long v, float& lo, float& hi) {
    asm("mov.b64 {%0, %1}, %2;" : "=f"(lo), "=f"(hi) : "l"(v));
}
__device__ __forceinline__ unsigned long long fma2(
    unsigned long long a, unsigned long long b, unsigned long long c) {
    unsigned long long d;
    asm("fma.rn.f32x2 %0, %1, %2, %3;" : "=l"(d) : "l"(a), "l"(b), "l"(c));
    return d;
}

// ---------------- one-pass padded-CSR build: 4 items/thread (MLP 4) ---------
// EE % 4 == 0 and (EE+NN) % 4 == 0, so the int4 fast path and the self-loop
// tail both handle exactly 4 valid items per thread.
__global__ void k_build(const int* __restrict__ src, const int* __restrict__ dst) {
    int t = blockIdx.x * blockDim.x + threadIdx.x;
    if (t >= (EE + NN) / 4) return;
    int base = t * 4;
    if (base < EE) {
        int4 s4 = ((const int4*)src)[t];
        int4 d4 = ((const int4*)dst)[t];
        int p0 = atomicAdd(&g_deg[d4.x], 1);
        int p1 = atomicAdd(&g_deg[d4.y], 1);
        int p2 = atomicAdd(&g_deg[d4.z], 1);
        int p3 = atomicAdd(&g_deg[d4.w], 1);
        if (p0 < CAP) g_bkt[d4.x * CAP + p0] = s4.x;
        if (p1 < CAP) g_bkt[d4.y * CAP + p1] = s4.y;
        if (p2 < CAP) g_bkt[d4.z * CAP + p2] = s4.z;
        if (p3 < CAP) g_bkt[d4.w * CAP + p3] = s4.w;
    } else {
#pragma unroll
        for (int j = 0; j < 4; j++) {
            int d = base - EE + j;                 // self-loop
            int pos = atomicAdd(&g_deg[d], 1);
            if (pos < CAP) g_bkt[d * CAP + pos] = d;
        }
    }
}

// ---------------- layer-1 node transforms: f32x2 packed FMA -----------------
__global__ void __launch_bounds__(256) k_transform1(
    const float* __restrict__ x,
    const float* __restrict__ Wl, const float* __restrict__ bl,
    const float* __restrict__ Wr, const float* __restrict__ br)
{
    __shared__ float xs[NPB * DIN];
    int t = threadIdx.x;
    const float* W;
    int c;
    float b;
    if (t < F) { W = Wl; c = t;     b = bl[c]; }
    else       { W = Wr; c = t - F; b = br[c]; }

    unsigned long long w2[DIN / 2];
#pragma unroll
    for (int k = 0; k < DIN / 2; k++)
        w2[k] = pk2(W[(2 * k) * F + c], W[(2 * k + 1) * F + c]);

    int n0 = blockIdx.x * NPB;
    for (int j = t; j < NPB * DIN; j += 256) xs[j] = x[n0 * DIN + j];
    __syncthreads();

    const float2* xs2 = (const float2*)xs;
    for (int i = 0; i < NPB; i++) {
        unsigned long long acc = pk2(b, 0.f);
        const float2* xrow = xs2 + i * (DIN / 2);
#pragma unroll
        for (int k = 0; k < DIN / 2; k++) {
            float2 xv = xrow[k];
            acc = fma2(pk2(xv.x, xv.y), w2[k], acc);
        }
        float lo, hi;
        upk2(acc, lo, hi);
        float v = lo + hi;
        int node = n0 + i;
        if (t < F) g_xl1h[node * F + c] = __float2half_rn(v);
        else       g_xr1h[node * F + c] = __float2half_rn(v);
    }
}

// ---------------- layer-1 aggregation: 2 edges/warp, 8 ch/lane --------------
// lane = (edge slot eo = lane>>4, chunk sub = lane&15). Each lane owns 8
// consecutive channels (uint4 = 16B); a half-warp covers one full 256B row.
// Head = sub>>1 spans a lane pair -> ONE shfl per edge for the logit.
__global__ void __launch_bounds__(256) k_agg1(
    const float* __restrict__ att,  const float* __restrict__ bias,
    const float* __restrict__ Wl2, const float* __restrict__ bl2,
    const float* __restrict__ Wr2, const float* __restrict__ br2)
{
    int w = (blockIdx.x * 256 + threadIdx.x) >> 5;
    if (w >= NN) return;
    int lane = threadIdx.x & 31;
    int eo  = lane >> 4;     // edge slot 0/1
    int sub = lane & 15;     // 8-channel chunk
    int d = w;

    const uint4* xlp = (const uint4*)g_xl1h;     // 16 uint4 per node row

    uint4 xrr = ((const uint4*)g_xr1h)[d * 16 + sub];
    __half2 xr2[4] = { *(__half2*)&xrr.x, *(__half2*)&xrr.y,
                       *(__half2*)&xrr.z, *(__half2*)&xrr.w };
    const float* attp = att + sub * 8;
    __half2 a2[4];
#pragma unroll
    for (int j = 0; j < 4; j++) a2[j] = __floats2half2_rn(attp[2*j], attp[2*j+1]);
    const __half2 c02 = __float2half2_rn(0.2f);
    const __half2 hz  = __float2half2_rn(0.f);

    int deg = g_deg[d];
    if (deg > CAP) deg = CAP;
    const int* bkt = &g_bkt[d * CAP];

    float l = 0.f;
    float acc[8];
#pragma unroll
    for (int c = 0; c < 8; c++) acc[c] = 0.f;

    // pipelined 2-edge loop
    int idx = eo;
    bool v = (idx < deg);
    int s = v ? bkt[idx] : 0;
    uint4 r = xlp[s * 16 + sub];
    for (int i = 0; i < deg; i += 2) {
        bool vc = v;
        uint4 rc = r;
        int ni = i + 2 + eo;
        v = (ni < deg);
        int ns = v ? bkt[ni] : 0;
        r = xlp[ns * 16 + sub];                  // prefetch (row 0 safe)

        __half2 h0 = *(__half2*)&rc.x, h1 = *(__half2*)&rc.y;
        __half2 h2 = *(__half2*)&rc.z, h3 = *(__half2*)&rc.w;
        __half2 pacc = hz;
        {
            __half2 vv, t;
            vv = __hadd2(h0, xr2[0]); t = __hmax2(vv, __hmul2(vv, c02)); pacc = __hfma2(t, a2[0], pacc);
            vv = __hadd2(h1, xr2[1]); t = __hmax2(vv, __hmul2(vv, c02)); pacc = __hfma2(t, a2[1], pacc);
            vv = __hadd2(h2, xr2[2]); t = __hmax2(vv, __hmul2(vv, c02)); pacc = __hfma2(t, a2[2], pacc);
            vv = __hadd2(h3, xr2[3]); t = __hmax2(vv, __hmul2(vv, c02)); pacc = __hfma2(t, a2[3], pacc);
        }
        float2 pf = __half22float2(pacc);
        float p = pf.x + pf.y;
        p += __shfl_xor_sync(0xffffffffu, p, 1);  // complete the 16-ch head
        float cc = vc ? __expf(p) : 0.f;
        l += cc;
        float2 f0 = __half22float2(h0), f1 = __half22float2(h1);
        float2 f2 = __half22float2(h2), f3 = __half22float2(h3);
        acc[0] = fmaf(cc, f0.x, acc[0]); acc[1] = fmaf(cc, f0.y, acc[1]);
        acc[2] = fmaf(cc, f1.x, acc[2]); acc[3] = fmaf(cc, f1.y, acc[3]);
        acc[4] = fmaf(cc, f2.x, acc[4]); acc[5] = fmaf(cc, f2.y, acc[5]);
        acc[6] = fmaf(cc, f3.x, acc[6]); acc[7] = fmaf(cc, f3.y, acc[7]);
    }

    // merge the two edge slots (xor 16)
    l += __shfl_xor_sync(0xffffffffu, l, 16);
#pragma unroll
    for (int c = 0; c < 8; c++)
        acc[c] += __shfl_xor_sync(0xffffffffu, acc[c], 16);

    // epilogue: normalize, +bias, elu, layer-2 dots (channels sub*8..sub*8+7)
    float inv = 1.f / l;
    float4 b0 = ((const float4*)bias)[sub * 2],  b1 = ((const float4*)bias)[sub * 2 + 1];
    float4 wl0 = ((const float4*)Wl2)[sub * 2],  wl1 = ((const float4*)Wl2)[sub * 2 + 1];
    float4 wr0 = ((const float4*)Wr2)[sub * 2],  wr1 = ((const float4*)Wr2)[sub * 2 + 1];
    float bb[8]  = { b0.x, b0.y, b0.z, b0.w, b1.x, b1.y, b1.z, b1.w };
    float wl[8]  = { wl0.x, wl0.y, wl0.z, wl0.w, wl1.x, wl1.y, wl1.z, wl1.w };
    float wr[8]  = { wr0.x, wr0.y, wr0.z, wr0.w, wr1.x, wr1.y, wr1.z, wr1.w };
    float pl = 0.f, pr = 0.f;
#pragma unroll
    for (int c = 0; c < 8; c++) {
        float hv = fmaf(acc[c], inv, bb[c]);
        hv = (hv > 0.f) ? hv : expm1f(hv);
        pl = fmaf(hv, wl[c], pl);
        pr = fmaf(hv, wr[c], pr);
    }
#pragma unroll
    for (int off = 1; off <= 8; off <<= 1) {
        pl += __shfl_xor_sync(0xffffffffu, pl, off);
        pr += __shfl_xor_sync(0xffffffffu, pr, off);
    }
    if (lane == 0) {
        g_xl2[d] = pl + bl2[0];
        g_xr2[d] = pr + br2[0];
    }
}

// ---------------- layer-2 aggregation: 8 lanes per node ---------------------
// Also zeroes g_deg (last consumer) so the next call starts clean.
__global__ void __launch_bounds__(256) k_agg2(
    const float* __restrict__ att2, const float* __restrict__ bias2,
    float* __restrict__ out)
{
    int gid = blockIdx.x * 256 + threadIdx.x;
    int w = gid >> 3;                 // 8 lanes per node, groups warp-aligned
    if (w >= NN) return;
    int sub = gid & 7;

    float xr = g_xr2[w];
    float a = att2[0];
    int deg = g_deg[w];
    if (deg > CAP) deg = CAP;
    const int* bkt = &g_bkt[w * CAP];

    float den = 0.f, num = 0.f;
    for (int i = sub; i < deg; i += 8) {
        int s = bkt[i];
        float v = g_xl2[s];
        float c = __expf(a * lrelu(v + xr));
        den += c;
        num = fmaf(c, v, num);
    }
#pragma unroll
    for (int off = 4; off; off >>= 1) {
        den += __shfl_xor_sync(0xffffffffu, den, off);
        num += __shfl_xor_sync(0xffffffffu, num, off);
    }
    if (sub == 0) {
        out[w] = num / den + bias2[0];
        g_deg[w] = 0;                 // clean state for next call
    }
}

// ---------------- launcher --------------------------------------------------
extern "C" void kernel_launch(void* const* d_in, const int* in_sizes, int n_in,
                              void* d_out, int out_size)
{
    const float* x     = (const float*)d_in[0];
    const int*   src   = (const int*)  d_in[1];
    const int*   dst   = (const int*)  d_in[2];
    const float* Wl1   = (const float*)d_in[3];
    const float* bl1   = (const float*)d_in[4];
    const float* Wr1   = (const float*)d_in[5];
    const float* br1   = (const float*)d_in[6];
    const float* att1  = (const float*)d_in[7];
    const float* bias1 = (const float*)d_in[8];
    const float* Wl2   = (const float*)d_in[9];
    const float* bl2   = (const float*)d_in[10];
    const float* Wr2   = (const float*)d_in[11];
    const float* br2   = (const float*)d_in[12];
    const float* att2  = (const float*)d_in[13];
    const float* bias2 = (const float*)d_in[14];
    float* out = (float*)d_out;

    static cudaStream_t s2 = nullptr;
    static cudaEvent_t evFork = nullptr, evJoin = nullptr;
    if (!s2) {
        cudaStreamCreateWithFlags(&s2, cudaStreamNonBlocking);
        cudaEventCreateWithFlags(&evFork, cudaEventDisableTiming);
        cudaEventCreateWithFlags(&evJoin, cudaEventDisableTiming);
    }

    // fork: transform1 runs concurrently with the one-pass bucket build
    cudaEventRecord(evFork, 0);
    cudaStreamWaitEvent(s2, evFork, 0);
    k_transform1<<<NN / NPB, 256, 0, s2>>>(x, Wl1, bl1, Wr1, br1);
    cudaEventRecord(evJoin, s2);

    k_build<<<((EE + NN) / 4 + 255) / 256, 256>>>(src, dst);

    // join, then aggregation
    cudaStreamWaitEvent(0, evJoin, 0);
    k_agg1<<<NN / 8, 256>>>(att1, bias1, Wl2, bl2, Wr2, br2);
    k_agg2<<<(NN * 8 + 255) / 256, 256>>>(att2, bias2, out);
}